// round 2
// baseline (speedup 1.0000x reference)
#include <cuda_runtime.h>

#define NG 32
#define NN 2048
#define NT 65536           // NG*NN
#define NE 1048576
#define NHEADS 8
#define F 12               // GAT_OUT
#define FH 96              // NHEADS*F
#define OUTC 9

// ---------------- scratch (static device memory only) ----------------
__device__ __align__(16) float g_xp[NT * FH];   // projected features [n][h][c]
__device__ float g_asrc[NT * NHEADS];
__device__ float g_adst[NT * NHEADS];
__device__ int   g_deg[NT];
__device__ int   g_off[NT + 1];
__device__ int   g_cur[NT];
__device__ int   g_csr[NE];            // src ids grouped by dst
__device__ __align__(16) float g_post[F * NT];       // post log_softmax, channel-major [t][gn]
__device__ __align__(16) float g_wT1[NN * 128];      // w_ih1^T  [n][j]
__device__ __align__(16) float g_wT2[128 * 512];     // w_hh2^T  [k][j]
__device__ __align__(16) float g_xp1[F * NG * 128];  // LSTM1 input projection
__device__ __align__(16) float g_hs1[F * NG * 32];
__device__ __align__(16) float g_xp2[F * NG * 512];  // LSTM2 input projection
__device__ __align__(16) float g_hs2[F * NG * 128];
__device__ __align__(16) float g_h2[NG * 128];
__device__ __align__(16) float g_c2[NG * 128];

__device__ __forceinline__ float lrelu(float v) { return v > 0.f ? v : 0.2f * v; }
__device__ __forceinline__ float sigf(float v) { return 1.0f / (1.0f + __expf(-v)); }

// ---------------- init: zero deg + lstm2 state ----------------
__global__ void k_init() {
    int i = blockIdx.x * blockDim.x + threadIdx.x;
    if (i < NT) g_deg[i] = 0;
    if (i < NG * 128) { g_h2[i] = 0.f; g_c2[i] = 0.f; }
}

// ---------------- xp = x @ W_gat, plus attention logits ----------------
__global__ void k_xp(const float* __restrict__ x, const float* __restrict__ W,
                     const float* __restrict__ av_s, const float* __restrict__ av_d) {
    __shared__ float Ws[F * FH];
    __shared__ float as_s[NHEADS * F], ad_s[NHEADS * F];
    for (int i = threadIdx.x; i < F * FH; i += blockDim.x) Ws[i] = W[i];
    for (int i = threadIdx.x; i < NHEADS * F; i += blockDim.x) { as_s[i] = av_s[i]; ad_s[i] = av_d[i]; }
    __syncthreads();

    int gid = blockIdx.x * blockDim.x + threadIdx.x;   // n*8 + h
    int n = gid >> 3, h = gid & 7;
    const float4* xv = reinterpret_cast<const float4*>(x + n * F);
    float4 v0 = xv[0], v1 = xv[1], v2 = xv[2];
    float xr[F] = {v0.x, v0.y, v0.z, v0.w, v1.x, v1.y, v1.z, v1.w, v2.x, v2.y, v2.z, v2.w};

    float o[F];
    float sa = 0.f, sd = 0.f;
#pragma unroll
    for (int c = 0; c < F; c++) {
        float s = 0.f;
#pragma unroll
        for (int k = 0; k < F; k++) s += xr[k] * Ws[k * FH + h * F + c];
        o[c] = s;
        sa += s * as_s[h * F + c];
        sd += s * ad_s[h * F + c];
    }
    float4* op = reinterpret_cast<float4*>(g_xp + n * FH + h * F);
    op[0] = make_float4(o[0], o[1], o[2], o[3]);
    op[1] = make_float4(o[4], o[5], o[6], o[7]);
    op[2] = make_float4(o[8], o[9], o[10], o[11]);
    g_asrc[gid] = sa;
    g_adst[gid] = sd;
}

// ---------------- CSR build (edge_index is int32: JAX default config disables x64) ----------------
__global__ void k_hist(const int* __restrict__ ei) {
    int e = blockIdx.x * blockDim.x + threadIdx.x;
    if (e < NE) atomicAdd(&g_deg[ei[NE + e]], 1);
}

__global__ void k_scan() {
    int tid = threadIdx.x;            // 1024 threads, 64 elems each
    int base = tid * 64;
    int s = 0;
    for (int i = 0; i < 64; i++) s += g_deg[base + i];
    __shared__ int sh[1024];
    sh[tid] = s;
    __syncthreads();
    for (int off = 1; off < 1024; off <<= 1) {
        int v = (tid >= off) ? sh[tid - off] : 0;
        __syncthreads();
        sh[tid] += v;
        __syncthreads();
    }
    int run = (tid == 0) ? 0 : sh[tid - 1];
    for (int i = 0; i < 64; i++) {
        g_off[base + i] = run;
        g_cur[base + i] = run;
        run += g_deg[base + i];
    }
    if (tid == 1023) g_off[NT] = run;
}

__global__ void k_scatter(const int* __restrict__ ei) {
    int e = blockIdx.x * blockDim.x + threadIdx.x;
    if (e < NE) {
        int d = ei[NE + e];
        int s = ei[e];
        int pos = atomicAdd(&g_cur[d], 1);
        g_csr[pos] = s;
    }
}

// ---------------- GAT aggregation + head-mean + bias + BN + log_softmax ----------------
__global__ void k_gat(const float* __restrict__ bias, const float* __restrict__ gamma,
                      const float* __restrict__ beta, const float* __restrict__ mean,
                      const float* __restrict__ var) {
    __shared__ float sb[F], sg[F], sbe[F], smn[F], svr[F];
    if (threadIdx.x < F) {
        sb[threadIdx.x]  = bias[threadIdx.x];
        sg[threadIdx.x]  = gamma[threadIdx.x];
        sbe[threadIdx.x] = beta[threadIdx.x];
        smn[threadIdx.x] = mean[threadIdx.x];
        svr[threadIdx.x] = var[threadIdx.x];
    }
    __syncthreads();

    int gid = blockIdx.x * blockDim.x + threadIdx.x;   // n*8 + h
    int n = gid >> 3, h = gid & 7;
    float adn = g_adst[gid];
    float e_self = lrelu(g_asrc[gid] + adn);
    int st = g_off[n], en = g_off[n + 1];

    // pass A: segment max
    float m = e_self;
    for (int i = st; i < en; i++) {
        int s = g_csr[i];
        m = fmaxf(m, lrelu(g_asrc[s * NHEADS + h] + adn));
    }
    // pass B: exp-sum + weighted message accumulation
    float denom = 0.f;
    float acc[F];
#pragma unroll
    for (int c = 0; c < F; c++) acc[c] = 0.f;
    {
        float w = __expf(e_self - m);
        denom += w;
        const float4* xv = reinterpret_cast<const float4*>(g_xp + n * FH + h * F);
#pragma unroll
        for (int q = 0; q < 3; q++) {
            float4 xq = xv[q];
            acc[4 * q + 0] += w * xq.x; acc[4 * q + 1] += w * xq.y;
            acc[4 * q + 2] += w * xq.z; acc[4 * q + 3] += w * xq.w;
        }
    }
    for (int i = st; i < en; i++) {
        int s = g_csr[i];
        float w = __expf(lrelu(g_asrc[s * NHEADS + h] + adn) - m);
        denom += w;
        const float4* xv = reinterpret_cast<const float4*>(g_xp + s * FH + h * F);
#pragma unroll
        for (int q = 0; q < 3; q++) {
            float4 xq = xv[q];
            acc[4 * q + 0] += w * xq.x; acc[4 * q + 1] += w * xq.y;
            acc[4 * q + 2] += w * xq.z; acc[4 * q + 3] += w * xq.w;
        }
    }
    float inv = 1.f / (denom + 1e-16f);
#pragma unroll
    for (int c = 0; c < F; c++) acc[c] *= inv;

    // mean over 8 heads (lanes of the same node are adjacent)
#pragma unroll
    for (int s = 4; s > 0; s >>= 1)
#pragma unroll
        for (int c = 0; c < F; c++) acc[c] += __shfl_xor_sync(0xffffffffu, acc[c], s);

    if (h == 0) {
        float v[F];
#pragma unroll
        for (int c = 0; c < F; c++) {
            float t = acc[c] * 0.125f + sb[c];
            v[c] = (t - smn[c]) * rsqrtf(svr[c] + 1e-5f) * sg[c] + sbe[c];
        }
        float mx = v[0];
#pragma unroll
        for (int c = 1; c < F; c++) mx = fmaxf(mx, v[c]);
        float ssum = 0.f;
#pragma unroll
        for (int c = 0; c < F; c++) ssum += __expf(v[c] - mx);
        float lz = mx + __logf(ssum);
#pragma unroll
        for (int c = 0; c < F; c++) g_post[c * NT + n] = v[c] - lz;
    }
}

// ---------------- weight transposes for coalescing ----------------
__global__ void k_trans(const float* __restrict__ w1, const float* __restrict__ w2) {
    int i = blockIdx.x * blockDim.x + threadIdx.x;   // 262144 threads
    if (i < NN * 128) { int n = i >> 7, j = i & 127; g_wT1[i] = w1[j * NN + n]; }
    if (i < 128 * 512) { int k = i >> 9, j = i & 511; g_wT2[i] = w2[j * 128 + k]; }
}

// ---------------- LSTM1 input projection (all 12 timesteps) ----------------
__global__ void k_xproj1(const float* __restrict__ bih1, const float* __restrict__ bhh1) {
    // grid 96: t = blk>>3, 4 batches per block; 128 threads = j
    int t = blockIdx.x >> 3;
    int bs = (blockIdx.x & 7) * 4;
    __shared__ float sp[4][256];
    float acc[4] = {0.f, 0.f, 0.f, 0.f};
    for (int n0 = 0; n0 < NN; n0 += 256) {
        __syncthreads();
        for (int i = threadIdx.x; i < 4 * 256; i += 128) {
            int q = i >> 8, ii = i & 255;
            sp[q][ii] = g_post[t * NT + (bs + q) * NN + n0 + ii];
        }
        __syncthreads();
#pragma unroll 4
        for (int ii = 0; ii < 256; ii++) {
            float w = g_wT1[(n0 + ii) * 128 + threadIdx.x];
            acc[0] += sp[0][ii] * w;
            acc[1] += sp[1][ii] * w;
            acc[2] += sp[2][ii] * w;
            acc[3] += sp[3][ii] * w;
        }
    }
    float bia = bih1[threadIdx.x] + bhh1[threadIdx.x];
#pragma unroll
    for (int q = 0; q < 4; q++)
        g_xp1[t * (NG * 128) + (bs + q) * 128 + threadIdx.x] = acc[q] + bia;
}

// ---------------- LSTM1 recurrence (single block, sequential t) ----------------
__global__ void k_lstm1(const float* __restrict__ whh1) {
    __shared__ float wT[32 * 128];   // [k][j]
    __shared__ float h1[NG * 32], c1[NG * 32];
    __shared__ float gs[NG * 128];
    int tid = threadIdx.x;           // 1024
    for (int i = tid; i < 4096; i += 1024) {
        int j = i >> 5, k = i & 31;
        wT[k * 128 + j] = whh1[i];
    }
    h1[tid] = 0.f; c1[tid] = 0.f;
    __syncthreads();

    for (int t = 0; t < F; t++) {
#pragma unroll
        for (int p = 0; p < 4; p++) {
            int g = p * 1024 + tid;
            int b = g >> 7, j = g & 127;
            float val = g_xp1[t * 4096 + g];
#pragma unroll
            for (int k = 0; k < 32; k++) val += h1[b * 32 + k] * wT[k * 128 + j];
            gs[g] = val;
        }
        __syncthreads();
        {
            int b = tid >> 5, jh = tid & 31;
            int base = b * 128 + jh;
            float ig = gs[base], fg = gs[base + 32], gg = gs[base + 64], og = gs[base + 96];
            float cc = sigf(fg) * c1[tid] + sigf(ig) * tanhf(gg);
            float hh = sigf(og) * tanhf(cc);
            c1[tid] = cc;
            h1[tid] = hh;
            g_hs1[t * 1024 + tid] = hh;
        }
        __syncthreads();
    }
}

// ---------------- LSTM2 input projection ----------------
__global__ void k_xproj2(const float* __restrict__ wih2, const float* __restrict__ bih2,
                         const float* __restrict__ bhh2) {
    int idx = blockIdx.x * blockDim.x + threadIdx.x;   // 12*32*512
    if (idx >= F * NG * 512) return;
    int t = idx / (NG * 512);
    int r = idx - t * (NG * 512);
    int b = r >> 9, j = r & 511;
    float val = bih2[j] + bhh2[j];
#pragma unroll
    for (int k = 0; k < 32; k++) val += g_hs1[t * 1024 + b * 32 + k] * wih2[j * 32 + k];
    g_xp2[idx] = val;
}

// ---------------- LSTM2 recurrence step (32 blocks, one per batch) ----------------
__global__ void k_lstm2(int t) {
    int b = blockIdx.x;
    int tid = threadIdx.x;           // 256
    __shared__ float h2s[128];
    __shared__ float gs[512];
    if (tid < 128) h2s[tid] = g_h2[b * 128 + tid];
    __syncthreads();
    int j0 = tid, j1 = tid + 256;
    float v0 = g_xp2[t * (NG * 512) + b * 512 + j0];
    float v1 = g_xp2[t * (NG * 512) + b * 512 + j1];
#pragma unroll 4
    for (int k = 0; k < 128; k++) {
        float hk = h2s[k];
        v0 += hk * g_wT2[k * 512 + j0];
        v1 += hk * g_wT2[k * 512 + j1];
    }
    gs[j0] = v0;
    gs[j1] = v1;
    __syncthreads();
    if (tid < 128) {
        int jh = tid;
        float ig = gs[jh], fg = gs[128 + jh], gg = gs[256 + jh], og = gs[384 + jh];
        float cc = sigf(fg) * g_c2[b * 128 + jh] + sigf(ig) * tanhf(gg);
        float hh = sigf(og) * tanhf(cc);
        g_c2[b * 128 + jh] = cc;
        g_h2[b * 128 + jh] = hh;
        g_hs2[t * (NG * 128) + b * 128 + jh] = hh;
    }
}

// ---------------- final linear for last 9 timesteps ----------------
__global__ void k_final(const float* __restrict__ linw, const float* __restrict__ linb,
                        float* __restrict__ out) {
    int b = blockIdx.x >> 4;
    int c0 = (blockIdx.x & 15) * 128;
    __shared__ __align__(16) float sh[OUTC * 128];
    for (int i = threadIdx.x; i < OUTC * 128; i += blockDim.x) {
        int k = i >> 7, j = i & 127;
        sh[i] = g_hs2[(3 + k) * (NG * 128) + b * 128 + j];
    }
    __syncthreads();
    int warp = threadIdx.x >> 5, lane = threadIdx.x & 31;
    for (int idx = 0; idx < 16; idx++) {
        int n = c0 + warp * 16 + idx;
        float4 w4 = reinterpret_cast<const float4*>(linw + n * 128)[lane];
        float acc[OUTC];
#pragma unroll
        for (int k = 0; k < OUTC; k++) {
            float4 h4 = *reinterpret_cast<float4*>(&sh[k * 128 + lane * 4]);
            acc[k] = w4.x * h4.x + w4.y * h4.y + w4.z * h4.z + w4.w * h4.w;
        }
#pragma unroll
        for (int s = 16; s > 0; s >>= 1)
#pragma unroll
            for (int k = 0; k < OUTC; k++) acc[k] += __shfl_xor_sync(0xffffffffu, acc[k], s);
        if (lane == 0) {
            float lb = linb[n];
            float* o = out + (size_t)(b * NN + n) * OUTC;
#pragma unroll
            for (int k = 0; k < OUTC; k++) o[k] = acc[k] + lb;
        }
    }
}

// ---------------- launch ----------------
extern "C" void kernel_launch(void* const* d_in, const int* in_sizes, int n_in,
                              void* d_out, int out_size) {
    const float* x     = (const float*)d_in[0];
    const int*   ei    = (const int*)d_in[1];     // int32: JAX x64 disabled
    const float* Wg    = (const float*)d_in[2];
    const float* a_src = (const float*)d_in[3];
    const float* a_dst = (const float*)d_in[4];
    const float* gbias = (const float*)d_in[5];
    const float* gamma = (const float*)d_in[6];
    const float* beta  = (const float*)d_in[7];
    const float* mean  = (const float*)d_in[8];
    const float* var   = (const float*)d_in[9];
    const float* wih1  = (const float*)d_in[10];
    const float* whh1  = (const float*)d_in[11];
    const float* bih1  = (const float*)d_in[12];
    const float* bhh1  = (const float*)d_in[13];
    const float* wih2  = (const float*)d_in[14];
    const float* whh2  = (const float*)d_in[15];
    const float* bih2  = (const float*)d_in[16];
    const float* bhh2  = (const float*)d_in[17];
    const float* linw  = (const float*)d_in[18];
    const float* linb  = (const float*)d_in[19];
    float* out = (float*)d_out;

    k_init<<<NT / 256, 256>>>();
    k_xp<<<NT * NHEADS / 256, 256>>>(x, Wg, a_src, a_dst);
    k_hist<<<NE / 256, 256>>>(ei);
    k_scan<<<1, 1024>>>();
    k_scatter<<<NE / 256, 256>>>(ei);
    k_gat<<<NT * NHEADS / 256, 256>>>(gbias, gamma, beta, mean, var);
    k_trans<<<NN * 128 / 256, 256>>>(wih1, whh2);
    k_xproj1<<<96, 128>>>(bih1, bhh1);
    k_lstm1<<<1, 1024>>>(whh1);
    k_xproj2<<<(F * NG * 512 + 255) / 256, 256>>>(wih2, bih2, bhh2);
    for (int t = 0; t < F; t++) k_lstm2<<<NG, 256>>>(t);
    k_final<<<NG * 16, 256>>>(linw, linb, out);
}

// round 3
// speedup vs baseline: 1.4120x; 1.4120x over previous
#include <cuda_runtime.h>

#define NG 32
#define NN 2048
#define NT 65536           // NG*NN
#define NE 1048576
#define NHEADS 8
#define F 12               // GAT_OUT
#define FH 96              // NHEADS*F
#define OUTC 9

// ---------------- scratch (static device memory only) ----------------
__device__ __align__(16) float g_xp[NT * FH];   // projected features [n][h][c]
__device__ float g_asrc[NT * NHEADS];
__device__ float g_adst[NT * NHEADS];
__device__ int   g_deg[NT];
__device__ int   g_off[NT + 1];
__device__ int   g_cur[NT];
__device__ int   g_bsum[64];
__device__ int   g_bpre[64];
__device__ int   g_csr[NE];            // src ids grouped by dst
__device__ __align__(16) float g_post[F * NT];       // post log_softmax, channel-major [t][gn]
__device__ __align__(16) float g_wT1[NN * 128];      // w_ih1^T  [n][j]
__device__ __align__(16) float g_wT2[128 * 512];     // w_hh2^T  [k][j]
__device__ __align__(16) float g_xp1[F * NG * 128];  // LSTM1 input projection
__device__ __align__(16) float g_hs1[F * NG * 32];
__device__ __align__(16) float g_xp2[F * NG * 512];  // LSTM2 input projection
__device__ __align__(16) float g_hs2[F * NG * 128];
__device__ __align__(16) float g_h2[NG * 128];
__device__ __align__(16) float g_c2[NG * 128];

__device__ __forceinline__ float lrelu(float v) { return v > 0.f ? v : 0.2f * v; }
__device__ __forceinline__ float sigf(float v) { return 1.0f / (1.0f + __expf(-v)); }

// ---------------- init: zero deg + lstm2 state ----------------
__global__ void k_init() {
    int i = blockIdx.x * blockDim.x + threadIdx.x;
    if (i < NT) g_deg[i] = 0;
    if (i < NG * 128) { g_h2[i] = 0.f; g_c2[i] = 0.f; }
}

// ---------------- xp = x @ W_gat, plus attention logits ----------------
__global__ void k_xp(const float* __restrict__ x, const float* __restrict__ W,
                     const float* __restrict__ av_s, const float* __restrict__ av_d) {
    __shared__ float Ws[F * FH];
    __shared__ float as_s[NHEADS * F], ad_s[NHEADS * F];
    for (int i = threadIdx.x; i < F * FH; i += blockDim.x) Ws[i] = W[i];
    for (int i = threadIdx.x; i < NHEADS * F; i += blockDim.x) { as_s[i] = av_s[i]; ad_s[i] = av_d[i]; }
    __syncthreads();

    int gid = blockIdx.x * blockDim.x + threadIdx.x;   // n*8 + h
    int n = gid >> 3, h = gid & 7;
    const float4* xv = reinterpret_cast<const float4*>(x + n * F);
    float4 v0 = xv[0], v1 = xv[1], v2 = xv[2];
    float xr[F] = {v0.x, v0.y, v0.z, v0.w, v1.x, v1.y, v1.z, v1.w, v2.x, v2.y, v2.z, v2.w};

    float o[F];
    float sa = 0.f, sd = 0.f;
#pragma unroll
    for (int c = 0; c < F; c++) {
        float s = 0.f;
#pragma unroll
        for (int k = 0; k < F; k++) s += xr[k] * Ws[k * FH + h * F + c];
        o[c] = s;
        sa += s * as_s[h * F + c];
        sd += s * ad_s[h * F + c];
    }
    float4* op = reinterpret_cast<float4*>(g_xp + n * FH + h * F);
    op[0] = make_float4(o[0], o[1], o[2], o[3]);
    op[1] = make_float4(o[4], o[5], o[6], o[7]);
    op[2] = make_float4(o[8], o[9], o[10], o[11]);
    g_asrc[gid] = sa;
    g_adst[gid] = sd;
}

// ---------------- CSR build (edge_index is int32) ----------------
__global__ void k_hist(const int* __restrict__ ei) {
    int e = blockIdx.x * blockDim.x + threadIdx.x;
    if (e < NE) atomicAdd(&g_deg[ei[NE + e]], 1);
}

// stage 1: 64 blocks x 1024 threads, block-local exclusive scan of degrees
__global__ void k_scan1() {
    int tid = threadIdx.x;
    int g = blockIdx.x * 1024 + tid;
    int lane = tid & 31, wid = tid >> 5;
    int v = g_deg[g];
    int incl = v;
#pragma unroll
    for (int off = 1; off < 32; off <<= 1) {
        int t = __shfl_up_sync(0xffffffffu, incl, off);
        if (lane >= off) incl += t;
    }
    __shared__ int wsum[32];
    if (lane == 31) wsum[wid] = incl;
    __syncthreads();
    if (wid == 0) {
        int s = wsum[lane];
        int si = s;
#pragma unroll
        for (int off = 1; off < 32; off <<= 1) {
            int t = __shfl_up_sync(0xffffffffu, si, off);
            if (lane >= off) si += t;
        }
        wsum[lane] = si - s;   // exclusive warp prefix
    }
    __syncthreads();
    incl += wsum[wid];
    g_off[g] = incl - v;       // block-local exclusive
    if (tid == 1023) g_bsum[blockIdx.x] = incl;
}

// stage 2: single block of 64 threads scans the 64 block sums (exclusive)
__global__ void k_scan2() {
    int tid = threadIdx.x;     // 64
    int lane = tid & 31, wid = tid >> 5;
    int v = g_bsum[tid];
    int incl = v;
#pragma unroll
    for (int off = 1; off < 32; off <<= 1) {
        int t = __shfl_up_sync(0xffffffffu, incl, off);
        if (lane >= off) incl += t;
    }
    __shared__ int w0;
    if (wid == 0 && lane == 31) w0 = incl;
    __syncthreads();
    if (wid == 1) incl += w0;
    g_bpre[tid] = incl - v;
}

// stage 3: add block prefixes, produce g_off/g_cur; total is exactly NE
__global__ void k_scan3() {
    int g = blockIdx.x * 1024 + threadIdx.x;
    int o = g_off[g] + g_bpre[blockIdx.x];
    g_off[g] = o;
    g_cur[g] = o;
    if (g == 0) g_off[NT] = NE;
}

__global__ void k_scatter(const int* __restrict__ ei) {
    int e = blockIdx.x * blockDim.x + threadIdx.x;
    if (e < NE) {
        int d = ei[NE + e];
        int s = ei[e];
        int pos = atomicAdd(&g_cur[d], 1);
        g_csr[pos] = s;
    }
}

// ---------------- GAT aggregation + head-mean + bias + BN + log_softmax ----------------
__global__ void k_gat(const float* __restrict__ bias, const float* __restrict__ gamma,
                      const float* __restrict__ beta, const float* __restrict__ mean,
                      const float* __restrict__ var) {
    __shared__ float sb[F], sg[F], sbe[F], smn[F], svr[F];
    if (threadIdx.x < F) {
        sb[threadIdx.x]  = bias[threadIdx.x];
        sg[threadIdx.x]  = gamma[threadIdx.x];
        sbe[threadIdx.x] = beta[threadIdx.x];
        smn[threadIdx.x] = mean[threadIdx.x];
        svr[threadIdx.x] = var[threadIdx.x];
    }
    __syncthreads();

    int gid = blockIdx.x * blockDim.x + threadIdx.x;   // n*8 + h
    int n = gid >> 3, h = gid & 7;
    float adn = g_adst[gid];
    float e_self = lrelu(g_asrc[gid] + adn);
    int st = g_off[n], en = g_off[n + 1];

    // pass A: segment max
    float m = e_self;
    for (int i = st; i < en; i++) {
        int s = g_csr[i];
        m = fmaxf(m, lrelu(g_asrc[s * NHEADS + h] + adn));
    }
    // pass B: exp-sum + weighted message accumulation
    float denom = 0.f;
    float acc[F];
#pragma unroll
    for (int c = 0; c < F; c++) acc[c] = 0.f;
    {
        float w = __expf(e_self - m);
        denom += w;
        const float4* xv = reinterpret_cast<const float4*>(g_xp + n * FH + h * F);
#pragma unroll
        for (int q = 0; q < 3; q++) {
            float4 xq = xv[q];
            acc[4 * q + 0] += w * xq.x; acc[4 * q + 1] += w * xq.y;
            acc[4 * q + 2] += w * xq.z; acc[4 * q + 3] += w * xq.w;
        }
    }
    for (int i = st; i < en; i++) {
        int s = g_csr[i];
        float w = __expf(lrelu(g_asrc[s * NHEADS + h] + adn) - m);
        denom += w;
        const float4* xv = reinterpret_cast<const float4*>(g_xp + s * FH + h * F);
#pragma unroll
        for (int q = 0; q < 3; q++) {
            float4 xq = xv[q];
            acc[4 * q + 0] += w * xq.x; acc[4 * q + 1] += w * xq.y;
            acc[4 * q + 2] += w * xq.z; acc[4 * q + 3] += w * xq.w;
        }
    }
    float inv = 1.f / (denom + 1e-16f);
#pragma unroll
    for (int c = 0; c < F; c++) acc[c] *= inv;

    // mean over 8 heads (lanes of the same node are adjacent)
#pragma unroll
    for (int s = 4; s > 0; s >>= 1)
#pragma unroll
        for (int c = 0; c < F; c++) acc[c] += __shfl_xor_sync(0xffffffffu, acc[c], s);

    if (h == 0) {
        float v[F];
#pragma unroll
        for (int c = 0; c < F; c++) {
            float t = acc[c] * 0.125f + sb[c];
            v[c] = (t - smn[c]) * rsqrtf(svr[c] + 1e-5f) * sg[c] + sbe[c];
        }
        float mx = v[0];
#pragma unroll
        for (int c = 1; c < F; c++) mx = fmaxf(mx, v[c]);
        float ssum = 0.f;
#pragma unroll
        for (int c = 0; c < F; c++) ssum += __expf(v[c] - mx);
        float lz = mx + __logf(ssum);
#pragma unroll
        for (int c = 0; c < F; c++) g_post[c * NT + n] = v[c] - lz;
    }
}

// ---------------- weight transposes for coalescing ----------------
__global__ void k_trans(const float* __restrict__ w1, const float* __restrict__ w2) {
    int i = blockIdx.x * blockDim.x + threadIdx.x;   // 262144 threads
    if (i < NN * 128) { int n = i >> 7, j = i & 127; g_wT1[i] = w1[j * NN + n]; }
    if (i < 128 * 512) { int k = i >> 9, j = i & 511; g_wT2[i] = w2[j * 128 + k]; }
}

// ---------------- LSTM1 input projection (all 12 timesteps) ----------------
__global__ void k_xproj1(const float* __restrict__ bih1, const float* __restrict__ bhh1) {
    // grid 96: t = blk>>3, 4 batches per block; 128 threads = j
    int t = blockIdx.x >> 3;
    int bs = (blockIdx.x & 7) * 4;
    __shared__ float sp[4][256];
    float acc[4] = {0.f, 0.f, 0.f, 0.f};
    for (int n0 = 0; n0 < NN; n0 += 256) {
        __syncthreads();
        for (int i = threadIdx.x; i < 4 * 256; i += 128) {
            int q = i >> 8, ii = i & 255;
            sp[q][ii] = g_post[t * NT + (bs + q) * NN + n0 + ii];
        }
        __syncthreads();
#pragma unroll 4
        for (int ii = 0; ii < 256; ii++) {
            float w = g_wT1[(n0 + ii) * 128 + threadIdx.x];
            acc[0] += sp[0][ii] * w;
            acc[1] += sp[1][ii] * w;
            acc[2] += sp[2][ii] * w;
            acc[3] += sp[3][ii] * w;
        }
    }
    float bia = bih1[threadIdx.x] + bhh1[threadIdx.x];
#pragma unroll
    for (int q = 0; q < 4; q++)
        g_xp1[t * (NG * 128) + (bs + q) * 128 + threadIdx.x] = acc[q] + bia;
}

// ---------------- LSTM1 recurrence (single block, sequential t) ----------------
__global__ void k_lstm1(const float* __restrict__ whh1) {
    __shared__ float wT[32 * 128];   // [k][j]
    __shared__ float h1[NG * 32], c1[NG * 32];
    __shared__ float gs[NG * 128];
    int tid = threadIdx.x;           // 1024
    for (int i = tid; i < 4096; i += 1024) {
        int j = i >> 5, k = i & 31;
        wT[k * 128 + j] = whh1[i];
    }
    h1[tid] = 0.f; c1[tid] = 0.f;
    __syncthreads();

    for (int t = 0; t < F; t++) {
#pragma unroll
        for (int p = 0; p < 4; p++) {
            int g = p * 1024 + tid;
            int b = g >> 7, j = g & 127;
            float val = g_xp1[t * 4096 + g];
#pragma unroll
            for (int k = 0; k < 32; k++) val += h1[b * 32 + k] * wT[k * 128 + j];
            gs[g] = val;
        }
        __syncthreads();
        {
            int b = tid >> 5, jh = tid & 31;
            int base = b * 128 + jh;
            float ig = gs[base], fg = gs[base + 32], gg = gs[base + 64], og = gs[base + 96];
            float cc = sigf(fg) * c1[tid] + sigf(ig) * tanhf(gg);
            float hh = sigf(og) * tanhf(cc);
            c1[tid] = cc;
            h1[tid] = hh;
            g_hs1[t * 1024 + tid] = hh;
        }
        __syncthreads();
    }
}

// ---------------- LSTM2 input projection ----------------
__global__ void k_xproj2(const float* __restrict__ wih2, const float* __restrict__ bih2,
                         const float* __restrict__ bhh2) {
    int idx = blockIdx.x * blockDim.x + threadIdx.x;   // 12*32*512
    if (idx >= F * NG * 512) return;
    int t = idx / (NG * 512);
    int r = idx - t * (NG * 512);
    int b = r >> 9, j = r & 511;
    float val = bih2[j] + bhh2[j];
#pragma unroll
    for (int k = 0; k < 32; k++) val += g_hs1[t * 1024 + b * 32 + k] * wih2[j * 32 + k];
    g_xp2[idx] = val;
}

// ---------------- LSTM2 recurrence step (32 blocks, one per batch) ----------------
__global__ void k_lstm2(int t) {
    int b = blockIdx.x;
    int tid = threadIdx.x;           // 256
    __shared__ float h2s[128];
    __shared__ float gs[512];
    if (tid < 128) h2s[tid] = g_h2[b * 128 + tid];
    __syncthreads();
    int j0 = tid, j1 = tid + 256;
    float v0 = g_xp2[t * (NG * 512) + b * 512 + j0];
    float v1 = g_xp2[t * (NG * 512) + b * 512 + j1];
#pragma unroll 4
    for (int k = 0; k < 128; k++) {
        float hk = h2s[k];
        v0 += hk * g_wT2[k * 512 + j0];
        v1 += hk * g_wT2[k * 512 + j1];
    }
    gs[j0] = v0;
    gs[j1] = v1;
    __syncthreads();
    if (tid < 128) {
        int jh = tid;
        float ig = gs[jh], fg = gs[128 + jh], gg = gs[256 + jh], og = gs[384 + jh];
        float cc = sigf(fg) * g_c2[b * 128 + jh] + sigf(ig) * tanhf(gg);
        float hh = sigf(og) * tanhf(cc);
        g_c2[b * 128 + jh] = cc;
        g_h2[b * 128 + jh] = hh;
        g_hs2[t * (NG * 128) + b * 128 + jh] = hh;
    }
}

// ---------------- final linear for last 9 timesteps ----------------
__global__ void k_final(const float* __restrict__ linw, const float* __restrict__ linb,
                        float* __restrict__ out) {
    int b = blockIdx.x >> 4;
    int c0 = (blockIdx.x & 15) * 128;
    __shared__ __align__(16) float sh[OUTC * 128];
    for (int i = threadIdx.x; i < OUTC * 128; i += blockDim.x) {
        int k = i >> 7, j = i & 127;
        sh[i] = g_hs2[(3 + k) * (NG * 128) + b * 128 + j];
    }
    __syncthreads();
    int warp = threadIdx.x >> 5, lane = threadIdx.x & 31;
    for (int idx = 0; idx < 16; idx++) {
        int n = c0 + warp * 16 + idx;
        float4 w4 = reinterpret_cast<const float4*>(linw + n * 128)[lane];
        float acc[OUTC];
#pragma unroll
        for (int k = 0; k < OUTC; k++) {
            float4 h4 = *reinterpret_cast<float4*>(&sh[k * 128 + lane * 4]);
            acc[k] = w4.x * h4.x + w4.y * h4.y + w4.z * h4.z + w4.w * h4.w;
        }
#pragma unroll
        for (int s = 16; s > 0; s >>= 1)
#pragma unroll
            for (int k = 0; k < OUTC; k++) acc[k] += __shfl_xor_sync(0xffffffffu, acc[k], s);
        if (lane == 0) {
            float lb = linb[n];
            float* o = out + (size_t)(b * NN + n) * OUTC;
#pragma unroll
            for (int k = 0; k < OUTC; k++) o[k] = acc[k] + lb;
        }
    }
}

// ---------------- launch ----------------
extern "C" void kernel_launch(void* const* d_in, const int* in_sizes, int n_in,
                              void* d_out, int out_size) {
    const float* x     = (const float*)d_in[0];
    const int*   ei    = (const int*)d_in[1];     // int32: JAX x64 disabled
    const float* Wg    = (const float*)d_in[2];
    const float* a_src = (const float*)d_in[3];
    const float* a_dst = (const float*)d_in[4];
    const float* gbias = (const float*)d_in[5];
    const float* gamma = (const float*)d_in[6];
    const float* beta  = (const float*)d_in[7];
    const float* mean  = (const float*)d_in[8];
    const float* var   = (const float*)d_in[9];
    const float* wih1  = (const float*)d_in[10];
    const float* whh1  = (const float*)d_in[11];
    const float* bih1  = (const float*)d_in[12];
    const float* bhh1  = (const float*)d_in[13];
    const float* wih2  = (const float*)d_in[14];
    const float* whh2  = (const float*)d_in[15];
    const float* bih2  = (const float*)d_in[16];
    const float* bhh2  = (const float*)d_in[17];
    const float* linw  = (const float*)d_in[18];
    const float* linb  = (const float*)d_in[19];
    float* out = (float*)d_out;

    k_init<<<NT / 256, 256>>>();
    k_xp<<<NT * NHEADS / 256, 256>>>(x, Wg, a_src, a_dst);
    k_hist<<<NE / 256, 256>>>(ei);
    k_scan1<<<64, 1024>>>();
    k_scan2<<<1, 64>>>();
    k_scan3<<<64, 1024>>>();
    k_scatter<<<NE / 256, 256>>>(ei);
    k_gat<<<NT * NHEADS / 256, 256>>>(gbias, gamma, beta, mean, var);
    k_trans<<<NN * 128 / 256, 256>>>(wih1, whh2);
    k_xproj1<<<96, 128>>>(bih1, bhh1);
    k_lstm1<<<1, 1024>>>(whh1);
    k_xproj2<<<(F * NG * 512 + 255) / 256, 256>>>(wih2, bih2, bhh2);
    for (int t = 0; t < F; t++) k_lstm2<<<NG, 256>>>(t);
    k_final<<<NG * 16, 256>>>(linw, linb, out);
}

// round 4
// speedup vs baseline: 1.5573x; 1.1029x over previous
#include <cuda_runtime.h>

#define NG 32
#define NN 2048
#define NT 65536           // NG*NN
#define NE 1048576
#define NHEADS 8
#define F 12               // GAT_OUT
#define FH 96              // NHEADS*F
#define OUTC 9

// ---------------- scratch (static device memory only) ----------------
__device__ __align__(16) float g_xp[NT * FH];   // projected features [n][h][c]
__device__ float g_asrc[NT * NHEADS];
__device__ float g_adst[NT * NHEADS];
__device__ int   g_deg[NT];
__device__ int   g_off[NT + 1];
__device__ int   g_cur[NT];
__device__ int   g_bsum[64];
__device__ int   g_csr[NE];            // src ids grouped by dst
__device__ __align__(16) float g_post[F * NT];       // post log_softmax, channel-major [t][gn]
__device__ __align__(16) float g_wT1[NN * 128];      // w_ih1^T  [n][j]
__device__ __align__(16) float g_wT2[128 * 512];     // w_hh2^T  [k][j]
__device__ __align__(16) float g_xp1[F * NG * 128];  // LSTM1 input projection
__device__ __align__(16) float g_hs1[F * NG * 32];
__device__ __align__(16) float g_hs2[F * NG * 128];

__device__ __forceinline__ float lrelu(float v) { return v > 0.f ? v : 0.2f * v; }
__device__ __forceinline__ float sigf(float v) { return 1.0f / (1.0f + __expf(-v)); }

// ---------------- init: zero deg + weight transposes (merged) ----------------
__global__ void k_init(const float* __restrict__ w1, const float* __restrict__ w2) {
    int i = blockIdx.x * blockDim.x + threadIdx.x;   // 262144 threads
    if (i < NT) g_deg[i] = 0;
    if (i < NN * 128) { int n = i >> 7, j = i & 127; g_wT1[i] = w1[j * NN + n]; }
    if (i < 128 * 512) { int k = i >> 9, j = i & 511; g_wT2[i] = w2[j * 128 + k]; }
}

// ---------------- xp = x @ W_gat, plus attention logits ----------------
__global__ void k_xp(const float* __restrict__ x, const float* __restrict__ W,
                     const float* __restrict__ av_s, const float* __restrict__ av_d) {
    __shared__ float Ws[F * FH];
    __shared__ float as_s[NHEADS * F], ad_s[NHEADS * F];
    for (int i = threadIdx.x; i < F * FH; i += blockDim.x) Ws[i] = W[i];
    for (int i = threadIdx.x; i < NHEADS * F; i += blockDim.x) { as_s[i] = av_s[i]; ad_s[i] = av_d[i]; }
    __syncthreads();

    int gid = blockIdx.x * blockDim.x + threadIdx.x;   // n*8 + h
    int n = gid >> 3, h = gid & 7;
    const float4* xv = reinterpret_cast<const float4*>(x + n * F);
    float4 v0 = xv[0], v1 = xv[1], v2 = xv[2];
    float xr[F] = {v0.x, v0.y, v0.z, v0.w, v1.x, v1.y, v1.z, v1.w, v2.x, v2.y, v2.z, v2.w};

    float o[F];
    float sa = 0.f, sd = 0.f;
#pragma unroll
    for (int c = 0; c < F; c++) {
        float s = 0.f;
#pragma unroll
        for (int k = 0; k < F; k++) s += xr[k] * Ws[k * FH + h * F + c];
        o[c] = s;
        sa += s * as_s[h * F + c];
        sd += s * ad_s[h * F + c];
    }
    float4* op = reinterpret_cast<float4*>(g_xp + n * FH + h * F);
    op[0] = make_float4(o[0], o[1], o[2], o[3]);
    op[1] = make_float4(o[4], o[5], o[6], o[7]);
    op[2] = make_float4(o[8], o[9], o[10], o[11]);
    g_asrc[gid] = sa;
    g_adst[gid] = sd;
}

// ---------------- CSR build (edge_index is int32) ----------------
__global__ void k_hist(const int* __restrict__ ei) {
    int e = blockIdx.x * blockDim.x + threadIdx.x;
    if (e < NE) atomicAdd(&g_deg[ei[NE + e]], 1);
}

// stage 1: 64 blocks x 1024 threads, block-local exclusive scan of degrees
__global__ void k_scan1() {
    int tid = threadIdx.x;
    int g = blockIdx.x * 1024 + tid;
    int lane = tid & 31, wid = tid >> 5;
    int v = g_deg[g];
    int incl = v;
#pragma unroll
    for (int off = 1; off < 32; off <<= 1) {
        int t = __shfl_up_sync(0xffffffffu, incl, off);
        if (lane >= off) incl += t;
    }
    __shared__ int wsum[32];
    if (lane == 31) wsum[wid] = incl;
    __syncthreads();
    if (wid == 0) {
        int s = wsum[lane];
        int si = s;
#pragma unroll
        for (int off = 1; off < 32; off <<= 1) {
            int t = __shfl_up_sync(0xffffffffu, si, off);
            if (lane >= off) si += t;
        }
        wsum[lane] = si - s;   // exclusive warp prefix
    }
    __syncthreads();
    incl += wsum[wid];
    g_off[g] = incl - v;       // block-local exclusive
    if (tid == 1023) g_bsum[blockIdx.x] = incl;
}

// stage 2+3 merged: each block computes its own block-prefix from g_bsum, applies
__global__ void k_scan3() {
    __shared__ int tmp[64];
    __shared__ int pre;
    int tid = threadIdx.x;
    if (tid < 64) tmp[tid] = g_bsum[tid];
    __syncthreads();
    if (tid == 0) {
        int s = 0;
        int nb = blockIdx.x;
        for (int i = 0; i < nb; i++) s += tmp[i];
        pre = s;
    }
    __syncthreads();
    int g = blockIdx.x * 1024 + tid;
    int o = g_off[g] + pre;
    g_off[g] = o;
    g_cur[g] = o;
    if (g == 0) g_off[NT] = NE;
}

__global__ void k_scatter(const int* __restrict__ ei) {
    int e = blockIdx.x * blockDim.x + threadIdx.x;
    if (e < NE) {
        int d = ei[NE + e];
        int s = ei[e];
        int pos = atomicAdd(&g_cur[d], 1);
        g_csr[pos] = s;
    }
}

// ---- GAT aggregation (single pass, no max shift) + head-mean + bias + BN + log_softmax ----
// softmax weights are invariant to the max shift; logits ~ N(0,1.5) so exp() is safe in fp32.
__global__ void k_gat(const float* __restrict__ bias, const float* __restrict__ gamma,
                      const float* __restrict__ beta, const float* __restrict__ mean,
                      const float* __restrict__ var) {
    __shared__ float sb[F], sg[F], sbe[F], smn[F], svr[F];
    if (threadIdx.x < F) {
        sb[threadIdx.x]  = bias[threadIdx.x];
        sg[threadIdx.x]  = gamma[threadIdx.x];
        sbe[threadIdx.x] = beta[threadIdx.x];
        smn[threadIdx.x] = mean[threadIdx.x];
        svr[threadIdx.x] = var[threadIdx.x];
    }
    __syncthreads();

    int gid = blockIdx.x * blockDim.x + threadIdx.x;   // n*8 + h
    int n = gid >> 3, h = gid & 7;
    float adn = g_adst[gid];
    int st = g_off[n], en = g_off[n + 1];

    float denom = 0.f;
    float acc[F];
#pragma unroll
    for (int c = 0; c < F; c++) acc[c] = 0.f;

    // self loop
    {
        float w = __expf(lrelu(g_asrc[gid] + adn));
        denom += w;
        const float4* xv = reinterpret_cast<const float4*>(g_xp + n * FH + h * F);
#pragma unroll
        for (int q = 0; q < 3; q++) {
            float4 xq = xv[q];
            acc[4 * q + 0] += w * xq.x; acc[4 * q + 1] += w * xq.y;
            acc[4 * q + 2] += w * xq.z; acc[4 * q + 3] += w * xq.w;
        }
    }
    for (int i = st; i < en; i++) {
        int s = g_csr[i];
        float w = __expf(lrelu(g_asrc[s * NHEADS + h] + adn));
        denom += w;
        const float4* xv = reinterpret_cast<const float4*>(g_xp + s * FH + h * F);
#pragma unroll
        for (int q = 0; q < 3; q++) {
            float4 xq = xv[q];
            acc[4 * q + 0] += w * xq.x; acc[4 * q + 1] += w * xq.y;
            acc[4 * q + 2] += w * xq.z; acc[4 * q + 3] += w * xq.w;
        }
    }
    float inv = 1.f / (denom + 1e-16f);
#pragma unroll
    for (int c = 0; c < F; c++) acc[c] *= inv;

    // mean over 8 heads (lanes of the same node are adjacent)
#pragma unroll
    for (int s = 4; s > 0; s >>= 1)
#pragma unroll
        for (int c = 0; c < F; c++) acc[c] += __shfl_xor_sync(0xffffffffu, acc[c], s);

    if (h == 0) {
        float v[F];
#pragma unroll
        for (int c = 0; c < F; c++) {
            float t = acc[c] * 0.125f + sb[c];
            v[c] = (t - smn[c]) * rsqrtf(svr[c] + 1e-5f) * sg[c] + sbe[c];
        }
        float mx = v[0];
#pragma unroll
        for (int c = 1; c < F; c++) mx = fmaxf(mx, v[c]);
        float ssum = 0.f;
#pragma unroll
        for (int c = 0; c < F; c++) ssum += __expf(v[c] - mx);
        float lz = mx + __logf(ssum);
#pragma unroll
        for (int c = 0; c < F; c++) g_post[c * NT + n] = v[c] - lz;
    }
}

// ---------------- LSTM1 input projection (all 12 timesteps) ----------------
__global__ void k_xproj1(const float* __restrict__ bih1, const float* __restrict__ bhh1) {
    // grid 96: t = blk>>3, 4 batches per block; 128 threads = j
    int t = blockIdx.x >> 3;
    int bs = (blockIdx.x & 7) * 4;
    __shared__ float sp[4][256];
    float acc[4] = {0.f, 0.f, 0.f, 0.f};
    for (int n0 = 0; n0 < NN; n0 += 256) {
        __syncthreads();
        for (int i = threadIdx.x; i < 4 * 256; i += 128) {
            int q = i >> 8, ii = i & 255;
            sp[q][ii] = g_post[t * NT + (bs + q) * NN + n0 + ii];
        }
        __syncthreads();
#pragma unroll 4
        for (int ii = 0; ii < 256; ii++) {
            float w = g_wT1[(n0 + ii) * 128 + threadIdx.x];
            acc[0] += sp[0][ii] * w;
            acc[1] += sp[1][ii] * w;
            acc[2] += sp[2][ii] * w;
            acc[3] += sp[3][ii] * w;
        }
    }
    float bia = bih1[threadIdx.x] + bhh1[threadIdx.x];
#pragma unroll
    for (int q = 0; q < 4; q++)
        g_xp1[t * (NG * 128) + (bs + q) * 128 + threadIdx.x] = acc[q] + bia;
}

// ---------------- LSTM1 recurrence: single block, shuffle-based gates ----------------
__global__ void k_lstm1(const float* __restrict__ whh1) {
    __shared__ float h1s[NG][32];     // [b][k]
    __shared__ float gs[NG][128];     // [b][j]
    int tid = threadIdx.x;            // 1024
    int j = tid & 127, g = tid >> 7;  // j gate idx, g = batch group (4 batches)
    int lane = tid & 31;

    // per-thread w_hh1 row in registers: wreg[k] = whh1[j*32+k]
    float wreg[32];
    {
        const float4* wrow = reinterpret_cast<const float4*>(whh1 + j * 32);
#pragma unroll
        for (int q = 0; q < 8; q++) {
            float4 v = wrow[q];
            wreg[4 * q] = v.x; wreg[4 * q + 1] = v.y; wreg[4 * q + 2] = v.z; wreg[4 * q + 3] = v.w;
        }
    }
    h1s[tid >> 5][tid & 31] = 0.f;
    float c_reg = 0.f;                // cell state for (b=tid>>5, jh=tid&31)
    __syncthreads();

    for (int t = 0; t < F; t++) {
        float hreg[4], val[4];
#pragma unroll
        for (int m = 0; m < 4; m++) {
            hreg[m] = h1s[4 * g + m][lane];
            val[m] = g_xp1[t * 4096 + (4 * g + m) * 128 + j];
        }
#pragma unroll
        for (int k = 0; k < 32; k++) {
            float wk = wreg[k];
#pragma unroll
            for (int m = 0; m < 4; m++) {
                float hk = __shfl_sync(0xffffffffu, hreg[m], k);
                val[m] += hk * wk;
            }
        }
#pragma unroll
        for (int m = 0; m < 4; m++) gs[4 * g + m][j] = val[m];
        __syncthreads();
        {
            int b = tid >> 5, jh = tid & 31;
            float ig = gs[b][jh], fg = gs[b][32 + jh], gg = gs[b][64 + jh], og = gs[b][96 + jh];
            float cc = sigf(fg) * c_reg + sigf(ig) * tanhf(gg);
            c_reg = cc;
            float hh = sigf(og) * tanhf(cc);
            h1s[b][jh] = hh;
            g_hs1[t * 1024 + tid] = hh;
        }
        __syncthreads();
    }
}

// ---------------- LSTM2: single persistent launch, input proj folded in ----------------
__global__ void k_lstm2(const float* __restrict__ wih2, const float* __restrict__ bih2,
                        const float* __restrict__ bhh2) {
    int b = blockIdx.x;               // 32 blocks, one per batch
    int tid = threadIdx.x;            // 256
    __shared__ float h2s[128];
    __shared__ float gsm[512];
    __shared__ float xs[32];

    // preload w_ih2 rows for this thread's two gate indices (j0=tid, j1=tid+256)
    float wi0[32], wi1[32];
    {
        const float4* r0 = reinterpret_cast<const float4*>(wih2 + tid * 32);
        const float4* r1 = reinterpret_cast<const float4*>(wih2 + (tid + 256) * 32);
#pragma unroll
        for (int q = 0; q < 8; q++) {
            float4 v = r0[q], u = r1[q];
            wi0[4 * q] = v.x; wi0[4 * q + 1] = v.y; wi0[4 * q + 2] = v.z; wi0[4 * q + 3] = v.w;
            wi1[4 * q] = u.x; wi1[4 * q + 1] = u.y; wi1[4 * q + 2] = u.z; wi1[4 * q + 3] = u.w;
        }
    }
    float bb0 = bih2[tid] + bhh2[tid];
    float bb1 = bih2[tid + 256] + bhh2[tid + 256];
    float c_reg = 0.f;
    if (tid < 128) h2s[tid] = 0.f;

    for (int t = 0; t < F; t++) {
        if (tid < 32) xs[tid] = g_hs1[t * 1024 + b * 32 + tid];
        __syncthreads();
        float v0 = bb0, v1 = bb1;
#pragma unroll
        for (int k = 0; k < 32; k++) {
            float xk = xs[k];
            v0 += xk * wi0[k];
            v1 += xk * wi1[k];
        }
#pragma unroll 4
        for (int k = 0; k < 128; k++) {
            float hk = h2s[k];
            v0 += hk * g_wT2[k * 512 + tid];
            v1 += hk * g_wT2[k * 512 + tid + 256];
        }
        gsm[tid] = v0;
        gsm[tid + 256] = v1;
        __syncthreads();
        if (tid < 128) {
            float ig = gsm[tid], fg = gsm[128 + tid], gg = gsm[256 + tid], og = gsm[384 + tid];
            float cc = sigf(fg) * c_reg + sigf(ig) * tanhf(gg);
            c_reg = cc;
            float hh = sigf(og) * tanhf(cc);
            h2s[tid] = hh;
            if (t >= 3) g_hs2[t * (NG * 128) + b * 128 + tid] = hh;
        }
        __syncthreads();
    }
}

// ---------------- final linear for last 9 timesteps ----------------
__global__ void k_final(const float* __restrict__ linw, const float* __restrict__ linb,
                        float* __restrict__ out) {
    int b = blockIdx.x >> 4;
    int c0 = (blockIdx.x & 15) * 128;
    __shared__ __align__(16) float sh[OUTC * 128];
    for (int i = threadIdx.x; i < OUTC * 128; i += blockDim.x) {
        int k = i >> 7, j = i & 127;
        sh[i] = g_hs2[(3 + k) * (NG * 128) + b * 128 + j];
    }
    __syncthreads();
    int warp = threadIdx.x >> 5, lane = threadIdx.x & 31;
    for (int idx = 0; idx < 16; idx++) {
        int n = c0 + warp * 16 + idx;
        float4 w4 = reinterpret_cast<const float4*>(linw + n * 128)[lane];
        float acc[OUTC];
#pragma unroll
        for (int k = 0; k < OUTC; k++) {
            float4 h4 = *reinterpret_cast<float4*>(&sh[k * 128 + lane * 4]);
            acc[k] = w4.x * h4.x + w4.y * h4.y + w4.z * h4.z + w4.w * h4.w;
        }
#pragma unroll
        for (int s = 16; s > 0; s >>= 1)
#pragma unroll
            for (int k = 0; k < OUTC; k++) acc[k] += __shfl_xor_sync(0xffffffffu, acc[k], s);
        if (lane == 0) {
            float lb = linb[n];
            float* o = out + (size_t)(b * NN + n) * OUTC;
#pragma unroll
            for (int k = 0; k < OUTC; k++) o[k] = acc[k] + lb;
        }
    }
}

// ---------------- launch ----------------
extern "C" void kernel_launch(void* const* d_in, const int* in_sizes, int n_in,
                              void* d_out, int out_size) {
    const float* x     = (const float*)d_in[0];
    const int*   ei    = (const int*)d_in[1];     // int32: JAX x64 disabled
    const float* Wg    = (const float*)d_in[2];
    const float* a_src = (const float*)d_in[3];
    const float* a_dst = (const float*)d_in[4];
    const float* gbias = (const float*)d_in[5];
    const float* gamma = (const float*)d_in[6];
    const float* beta  = (const float*)d_in[7];
    const float* mean  = (const float*)d_in[8];
    const float* var   = (const float*)d_in[9];
    const float* wih1  = (const float*)d_in[10];
    const float* whh1  = (const float*)d_in[11];
    const float* bih1  = (const float*)d_in[12];
    const float* bhh1  = (const float*)d_in[13];
    const float* wih2  = (const float*)d_in[14];
    const float* whh2  = (const float*)d_in[15];
    const float* bih2  = (const float*)d_in[16];
    const float* bhh2  = (const float*)d_in[17];
    const float* linw  = (const float*)d_in[18];
    const float* linb  = (const float*)d_in[19];
    float* out = (float*)d_out;

    k_init<<<NN * 128 / 256, 256>>>(wih1, whh2);
    k_xp<<<NT * NHEADS / 256, 256>>>(x, Wg, a_src, a_dst);
    k_hist<<<NE / 256, 256>>>(ei);
    k_scan1<<<64, 1024>>>();
    k_scan3<<<64, 1024>>>();
    k_scatter<<<NE / 256, 256>>>(ei);
    k_gat<<<NT * NHEADS / 256, 256>>>(gbias, gamma, beta, mean, var);
    k_xproj1<<<96, 128>>>(bih1, bhh1);
    k_lstm1<<<1, 1024>>>(whh1);
    k_lstm2<<<NG, 256>>>(wih2, bih2, bhh2);
    k_final<<<NG * 16, 256>>>(linw, linb, out);
}

// round 5
// speedup vs baseline: 2.0996x; 1.3482x over previous
#include <cuda_runtime.h>
#include <cuda_fp16.h>

#define NG 32
#define NN 2048
#define NT 65536           // NG*NN
#define NE 1048576
#define NHEADS 8
#define F 12               // GAT_OUT
#define FH 96              // NHEADS*F
#define OUTC 9

// ---------------- scratch (static device memory only) ----------------
// per (n,h) 32B record: { asrc f32 | 12 x f16 channels | pad }
__device__ __align__(16) uint4 g_rec[NT * NHEADS * 2];
__device__ float g_adst[NT * NHEADS];
__device__ int   g_deg[NT];
__device__ int   g_off[NT + 1];
__device__ int   g_cur[NT];
__device__ int   g_bsum[64];
__device__ int   g_csr[NE];            // src ids grouped by dst
__device__ __align__(16) float g_post[F * NT];       // post log_softmax, channel-major [t][gn]
__device__ __align__(16) float g_wT1[NN * 128];      // w_ih1^T  [n][j]
__device__ __align__(16) float g_xp1[F * NG * 128];  // LSTM1 input projection
__device__ __align__(16) float g_hs1[F * NG * 32];
__device__ __align__(16) float g_hs2[F * NG * 128];

__device__ __forceinline__ float lrelu(float v) { return v > 0.f ? v : 0.2f * v; }
__device__ __forceinline__ float sigf(float v) { return 1.0f / (1.0f + __expf(-v)); }

// ---------------- prep: zero deg, transpose w_ih1, xp = x@W + logits, pack records ----------------
__global__ void k_prep(const float* __restrict__ x, const float* __restrict__ W,
                       const float* __restrict__ av_s, const float* __restrict__ av_d,
                       const float* __restrict__ w1) {
    __shared__ float Ws[F * FH];
    __shared__ float as_s[FH], ad_s[FH];
    for (int i = threadIdx.x; i < F * FH; i += blockDim.x) Ws[i] = W[i];
    for (int i = threadIdx.x; i < FH; i += blockDim.x) { as_s[i] = av_s[i]; ad_s[i] = av_d[i]; }
    __syncthreads();

    int gid = blockIdx.x * blockDim.x + threadIdx.x;   // 0 .. 524287 = n*8+h
    if (gid < NT) g_deg[gid] = 0;
    if (gid < NN * 128) { int n = gid >> 7, j = gid & 127; g_wT1[gid] = w1[j * NN + n]; }

    int n = gid >> 3, h = gid & 7;
    const float4* xv = reinterpret_cast<const float4*>(x + n * F);
    float4 v0 = xv[0], v1 = xv[1], v2 = xv[2];
    float xr[F] = {v0.x, v0.y, v0.z, v0.w, v1.x, v1.y, v1.z, v1.w, v2.x, v2.y, v2.z, v2.w};

    float o[F];
    float sa = 0.f, sd = 0.f;
#pragma unroll
    for (int c = 0; c < F; c++) {
        float s = 0.f;
#pragma unroll
        for (int k = 0; k < F; k++) s += xr[k] * Ws[k * FH + h * F + c];
        o[c] = s;
        sa += s * as_s[h * F + c];
        sd += s * ad_s[h * F + c];
    }
    uint4 r0, r1;
    r0.x = __float_as_uint(sa);
    __half2 p;
    p = __floats2half2_rn(o[0], o[1]);   r0.y = *reinterpret_cast<unsigned*>(&p);
    p = __floats2half2_rn(o[2], o[3]);   r0.z = *reinterpret_cast<unsigned*>(&p);
    p = __floats2half2_rn(o[4], o[5]);   r0.w = *reinterpret_cast<unsigned*>(&p);
    p = __floats2half2_rn(o[6], o[7]);   r1.x = *reinterpret_cast<unsigned*>(&p);
    p = __floats2half2_rn(o[8], o[9]);   r1.y = *reinterpret_cast<unsigned*>(&p);
    p = __floats2half2_rn(o[10], o[11]); r1.z = *reinterpret_cast<unsigned*>(&p);
    r1.w = 0u;
    g_rec[gid * 2]     = r0;
    g_rec[gid * 2 + 1] = r1;
    g_adst[gid] = sd;
}

// ---------------- CSR build (edge_index is int32) ----------------
__global__ void k_hist(const int* __restrict__ ei) {
    int e = blockIdx.x * blockDim.x + threadIdx.x;
    if (e < NE) atomicAdd(&g_deg[ei[NE + e]], 1);
}

__global__ void k_scan1() {
    int tid = threadIdx.x;
    int g = blockIdx.x * 1024 + tid;
    int lane = tid & 31, wid = tid >> 5;
    int v = g_deg[g];
    int incl = v;
#pragma unroll
    for (int off = 1; off < 32; off <<= 1) {
        int t = __shfl_up_sync(0xffffffffu, incl, off);
        if (lane >= off) incl += t;
    }
    __shared__ int wsum[32];
    if (lane == 31) wsum[wid] = incl;
    __syncthreads();
    if (wid == 0) {
        int s = wsum[lane];
        int si = s;
#pragma unroll
        for (int off = 1; off < 32; off <<= 1) {
            int t = __shfl_up_sync(0xffffffffu, si, off);
            if (lane >= off) si += t;
        }
        wsum[lane] = si - s;
    }
    __syncthreads();
    incl += wsum[wid];
    g_off[g] = incl - v;
    if (tid == 1023) g_bsum[blockIdx.x] = incl;
}

__global__ void k_scan3() {
    __shared__ int tmp[64];
    __shared__ int pre;
    int tid = threadIdx.x;
    if (tid < 64) tmp[tid] = g_bsum[tid];
    __syncthreads();
    if (tid == 0) {
        int s = 0;
        int nb = blockIdx.x;
        for (int i = 0; i < nb; i++) s += tmp[i];
        pre = s;
    }
    __syncthreads();
    int g = blockIdx.x * 1024 + tid;
    int o = g_off[g] + pre;
    g_off[g] = o;
    g_cur[g] = o;
    if (g == 0) g_off[NT] = NE;
}

__global__ void k_scatter(const int* __restrict__ ei) {
    int e = blockIdx.x * blockDim.x + threadIdx.x;
    if (e < NE) {
        int d = ei[NE + e];
        int s = ei[e];
        int pos = atomicAdd(&g_cur[d], 1);
        g_csr[pos] = s;
    }
}

// ---- GAT aggregation (single pass over packed 32B records) + head-mean + BN + log_softmax ----
__global__ void k_gat(const float* __restrict__ bias, const float* __restrict__ gamma,
                      const float* __restrict__ beta, const float* __restrict__ mean,
                      const float* __restrict__ var) {
    __shared__ float sb[F], sg[F], sbe[F], smn[F], svr[F];
    if (threadIdx.x < F) {
        sb[threadIdx.x]  = bias[threadIdx.x];
        sg[threadIdx.x]  = gamma[threadIdx.x];
        sbe[threadIdx.x] = beta[threadIdx.x];
        smn[threadIdx.x] = mean[threadIdx.x];
        svr[threadIdx.x] = var[threadIdx.x];
    }
    __syncthreads();

    int gid = blockIdx.x * blockDim.x + threadIdx.x;   // n*8 + h
    int n = gid >> 3, h = gid & 7;
    float adn = g_adst[gid];
    int st = g_off[n], en = g_off[n + 1];

    float denom = 0.f;
    float acc[F];
#pragma unroll
    for (int c = 0; c < F; c++) acc[c] = 0.f;

#define EDGE_ACC(rid)                                                          \
    {                                                                          \
        const uint4* rp = &g_rec[(unsigned)(rid) * 2u];                        \
        uint4 r0 = rp[0], r1 = rp[1];                                          \
        float w = __expf(lrelu(__uint_as_float(r0.x) + adn));                  \
        denom += w;                                                            \
        __half2 hp; float2 f2;                                                 \
        hp = *reinterpret_cast<__half2*>(&r0.y); f2 = __half22float2(hp);      \
        acc[0] += w * f2.x; acc[1] += w * f2.y;                                \
        hp = *reinterpret_cast<__half2*>(&r0.z); f2 = __half22float2(hp);      \
        acc[2] += w * f2.x; acc[3] += w * f2.y;                                \
        hp = *reinterpret_cast<__half2*>(&r0.w); f2 = __half22float2(hp);      \
        acc[4] += w * f2.x; acc[5] += w * f2.y;                                \
        hp = *reinterpret_cast<__half2*>(&r1.x); f2 = __half22float2(hp);      \
        acc[6] += w * f2.x; acc[7] += w * f2.y;                                \
        hp = *reinterpret_cast<__half2*>(&r1.y); f2 = __half22float2(hp);      \
        acc[8] += w * f2.x; acc[9] += w * f2.y;                                \
        hp = *reinterpret_cast<__half2*>(&r1.z); f2 = __half22float2(hp);      \
        acc[10] += w * f2.x; acc[11] += w * f2.y;                              \
    }

    EDGE_ACC(gid);                       // self loop
    for (int i = st; i < en; i++) {
        int s = g_csr[i];
        EDGE_ACC(s * NHEADS + h);
    }
#undef EDGE_ACC

    float inv = 1.f / (denom + 1e-16f);
#pragma unroll
    for (int c = 0; c < F; c++) acc[c] *= inv;

    // mean over 8 heads (lanes of same node adjacent)
#pragma unroll
    for (int s = 4; s > 0; s >>= 1)
#pragma unroll
        for (int c = 0; c < F; c++) acc[c] += __shfl_xor_sync(0xffffffffu, acc[c], s);

    if (h == 0) {
        float v[F];
#pragma unroll
        for (int c = 0; c < F; c++) {
            float t = acc[c] * 0.125f + sb[c];
            v[c] = (t - smn[c]) * rsqrtf(svr[c] + 1e-5f) * sg[c] + sbe[c];
        }
        float mx = v[0];
#pragma unroll
        for (int c = 1; c < F; c++) mx = fmaxf(mx, v[c]);
        float ssum = 0.f;
#pragma unroll
        for (int c = 0; c < F; c++) ssum += __expf(v[c] - mx);
        float lz = mx + __logf(ssum);
#pragma unroll
        for (int c = 0; c < F; c++) g_post[c * NT + n] = v[c] - lz;
    }
}

// ---------------- LSTM1 input projection (all 12 timesteps) ----------------
__global__ void k_xproj1(const float* __restrict__ bih1, const float* __restrict__ bhh1) {
    int t = blockIdx.x >> 3;
    int bs = (blockIdx.x & 7) * 4;
    __shared__ float sp[4][256];
    float acc[4] = {0.f, 0.f, 0.f, 0.f};
    for (int n0 = 0; n0 < NN; n0 += 256) {
        __syncthreads();
        for (int i = threadIdx.x; i < 4 * 256; i += 128) {
            int q = i >> 8, ii = i & 255;
            sp[q][ii] = g_post[t * NT + (bs + q) * NN + n0 + ii];
        }
        __syncthreads();
#pragma unroll 4
        for (int ii = 0; ii < 256; ii++) {
            float w = g_wT1[(n0 + ii) * 128 + threadIdx.x];
            acc[0] += sp[0][ii] * w;
            acc[1] += sp[1][ii] * w;
            acc[2] += sp[2][ii] * w;
            acc[3] += sp[3][ii] * w;
        }
    }
    float bia = bih1[threadIdx.x] + bhh1[threadIdx.x];
#pragma unroll
    for (int q = 0; q < 4; q++)
        g_xp1[t * (NG * 128) + (bs + q) * 128 + threadIdx.x] = acc[q] + bia;
}

// ---------------- LSTM1 recurrence: 32 blocks (one per batch) x 128 threads ----------------
__global__ void k_lstm1(const float* __restrict__ whh1) {
    int b = blockIdx.x, j = threadIdx.x;
    __shared__ __align__(16) float h1s[32];
    __shared__ float gs[128];
    float wreg[32];
    {
        const float4* wr = reinterpret_cast<const float4*>(whh1 + j * 32);
#pragma unroll
        for (int q = 0; q < 8; q++) {
            float4 v = wr[q];
            wreg[4 * q] = v.x; wreg[4 * q + 1] = v.y; wreg[4 * q + 2] = v.z; wreg[4 * q + 3] = v.w;
        }
    }
    float c_reg = 0.f;
    if (j < 32) h1s[j] = 0.f;
    __syncthreads();

    for (int t = 0; t < F; t++) {
        float v = g_xp1[t * 4096 + b * 128 + j];
        const float4* hv = reinterpret_cast<const float4*>(h1s);
#pragma unroll
        for (int q = 0; q < 8; q++) {
            float4 h4 = hv[q];
            v += h4.x * wreg[4 * q] + h4.y * wreg[4 * q + 1] + h4.z * wreg[4 * q + 2] + h4.w * wreg[4 * q + 3];
        }
        gs[j] = v;
        __syncthreads();
        if (j < 32) {
            float ig = gs[j], fg = gs[32 + j], gg = gs[64 + j], og = gs[96 + j];
            float cc = sigf(fg) * c_reg + sigf(ig) * tanhf(gg);
            c_reg = cc;
            float hh = sigf(og) * tanhf(cc);
            h1s[j] = hh;
            g_hs1[t * 1024 + b * 32 + j] = hh;
        }
        __syncthreads();
    }
}

// ---------------- LSTM2: 64 blocks, clusters of 2; weights staged in smem once ----------------
// block rank r handles hidden units jh in [64r, 64r+64) -> 256 gate rows, 256 threads (1 each).
#define LSTM2_SMEM (256 * 129 * 4)

__global__ void __cluster_dims__(2, 1, 1) __launch_bounds__(256, 1)
k_lstm2(const float* __restrict__ whh2, const float* __restrict__ wih2,
        const float* __restrict__ bih2, const float* __restrict__ bhh2) {
    extern __shared__ float wsm[];                  // [256 rows][129] padded
    __shared__ __align__(16) float h2buf[2][128];   // double-buffered full h
    __shared__ float gs[256];
    __shared__ __align__(16) float xs[32];

    int tid = threadIdx.x;
    int b = blockIdx.x >> 1;
    unsigned r;
    asm("mov.u32 %0, %%cluster_ctarank;" : "=r"(r));

    int gt = tid >> 6, l = tid & 63;
    int jh = (int)r * 64 + l;
    int jglob = gt * 128 + jh;

    // stage this block's 256 w_hh2 rows (row-major [j][k], direct)
    for (int idx = tid; idx < 256 * 128; idx += 256) {
        int jl = idx >> 7, k = idx & 127;
        int jg2 = (jl >> 6) * 128 + (int)r * 64 + (jl & 63);
        wsm[jl * 129 + k] = whh2[jg2 * 128 + k];
    }
    float wi[32];
    {
        const float4* wr = reinterpret_cast<const float4*>(wih2 + jglob * 32);
#pragma unroll
        for (int q = 0; q < 8; q++) {
            float4 v = wr[q];
            wi[4 * q] = v.x; wi[4 * q + 1] = v.y; wi[4 * q + 2] = v.z; wi[4 * q + 3] = v.w;
        }
    }
    float bb = bih2[jglob] + bhh2[jglob];
    float c_reg = 0.f;
    if (tid < 128) h2buf[0][tid] = 0.f;

    unsigned peer_h2;
    {
        unsigned a = (unsigned)__cvta_generic_to_shared(&h2buf[0][0]);
        asm("mapa.shared::cluster.u32 %0, %1, %2;" : "=r"(peer_h2) : "r"(a), "r"(r ^ 1u));
    }
    asm volatile("barrier.cluster.arrive.aligned;" ::: "memory");
    asm volatile("barrier.cluster.wait.aligned;" ::: "memory");

    const float* wrow = &wsm[tid * 129];
    for (int t = 0; t < F; t++) {
        int cur = t & 1, nxt = cur ^ 1;
        if (tid < 32) xs[tid] = g_hs1[t * 1024 + b * 32 + tid];
        __syncthreads();
        float v = bb;
#pragma unroll
        for (int q = 0; q < 8; q++) {
            float4 x4 = reinterpret_cast<const float4*>(xs)[q];
            v += x4.x * wi[4 * q] + x4.y * wi[4 * q + 1] + x4.z * wi[4 * q + 2] + x4.w * wi[4 * q + 3];
        }
        const float4* hv = reinterpret_cast<const float4*>(h2buf[cur]);
#pragma unroll
        for (int kk = 0; kk < 32; kk++) {
            float4 h4 = hv[kk];
            v += h4.x * wrow[4 * kk] + h4.y * wrow[4 * kk + 1]
               + h4.z * wrow[4 * kk + 2] + h4.w * wrow[4 * kk + 3];
        }
        gs[tid] = v;
        __syncthreads();
        if (tid < 64) {
            float ig = gs[tid], fg = gs[64 + tid], gg = gs[128 + tid], og = gs[192 + tid];
            float cc = sigf(fg) * c_reg + sigf(ig) * tanhf(gg);
            c_reg = cc;
            float hh = sigf(og) * tanhf(cc);
            int jc = (int)r * 64 + tid;
            h2buf[nxt][jc] = hh;
            asm volatile("st.shared::cluster.f32 [%0], %1;"
                         :: "r"(peer_h2 + (unsigned)((nxt * 128 + jc) * 4)), "f"(hh) : "memory");
            if (t >= 3) g_hs2[t * (NG * 128) + b * 128 + jc] = hh;
        }
        asm volatile("barrier.cluster.arrive.aligned;" ::: "memory");
        asm volatile("barrier.cluster.wait.aligned;" ::: "memory");
    }
}

// ---------------- final linear for last 9 timesteps ----------------
__global__ void k_final(const float* __restrict__ linw, const float* __restrict__ linb,
                        float* __restrict__ out) {
    int b = blockIdx.x >> 4;
    int c0 = (blockIdx.x & 15) * 128;
    __shared__ __align__(16) float sh[OUTC * 128];
    for (int i = threadIdx.x; i < OUTC * 128; i += blockDim.x) {
        int k = i >> 7, j = i & 127;
        sh[i] = g_hs2[(3 + k) * (NG * 128) + b * 128 + j];
    }
    __syncthreads();
    int warp = threadIdx.x >> 5, lane = threadIdx.x & 31;
    for (int idx = 0; idx < 16; idx++) {
        int n = c0 + warp * 16 + idx;
        float4 w4 = reinterpret_cast<const float4*>(linw + n * 128)[lane];
        float acc[OUTC];
#pragma unroll
        for (int k = 0; k < OUTC; k++) {
            float4 h4 = *reinterpret_cast<float4*>(&sh[k * 128 + lane * 4]);
            acc[k] = w4.x * h4.x + w4.y * h4.y + w4.z * h4.z + w4.w * h4.w;
        }
#pragma unroll
        for (int s = 16; s > 0; s >>= 1)
#pragma unroll
            for (int k = 0; k < OUTC; k++) acc[k] += __shfl_xor_sync(0xffffffffu, acc[k], s);
        if (lane == 0) {
            float lb = linb[n];
            float* o = out + (size_t)(b * NN + n) * OUTC;
#pragma unroll
            for (int k = 0; k < OUTC; k++) o[k] = acc[k] + lb;
        }
    }
}

// ---------------- launch ----------------
extern "C" void kernel_launch(void* const* d_in, const int* in_sizes, int n_in,
                              void* d_out, int out_size) {
    const float* x     = (const float*)d_in[0];
    const int*   ei    = (const int*)d_in[1];     // int32: JAX x64 disabled
    const float* Wg    = (const float*)d_in[2];
    const float* a_src = (const float*)d_in[3];
    const float* a_dst = (const float*)d_in[4];
    const float* gbias = (const float*)d_in[5];
    const float* gamma = (const float*)d_in[6];
    const float* beta  = (const float*)d_in[7];
    const float* mean  = (const float*)d_in[8];
    const float* var   = (const float*)d_in[9];
    const float* wih1  = (const float*)d_in[10];
    const float* whh1  = (const float*)d_in[11];
    const float* bih1  = (const float*)d_in[12];
    const float* bhh1  = (const float*)d_in[13];
    const float* wih2  = (const float*)d_in[14];
    const float* whh2  = (const float*)d_in[15];
    const float* bih2  = (const float*)d_in[16];
    const float* bhh2  = (const float*)d_in[17];
    const float* linw  = (const float*)d_in[18];
    const float* linb  = (const float*)d_in[19];
    float* out = (float*)d_out;

    cudaFuncSetAttribute(k_lstm2, cudaFuncAttributeMaxDynamicSharedMemorySize, LSTM2_SMEM);

    k_prep<<<NT * NHEADS / 256, 256>>>(x, Wg, a_src, a_dst, wih1);
    k_hist<<<NE / 256, 256>>>(ei);
    k_scan1<<<64, 1024>>>();
    k_scan3<<<64, 1024>>>();
    k_scatter<<<NE / 256, 256>>>(ei);
    k_gat<<<NT * NHEADS / 256, 256>>>(gbias, gamma, beta, mean, var);
    k_xproj1<<<96, 128>>>(bih1, bhh1);
    k_lstm1<<<NG, 128>>>(whh1);
    k_lstm2<<<NG * 2, 256, LSTM2_SMEM>>>(whh2, wih2, bih2, bhh2);
    k_final<<<NG * 16, 256>>>(linw, linb, out);
}

// round 6
// speedup vs baseline: 2.1655x; 1.0314x over previous
#include <cuda_runtime.h>
#include <cuda_fp16.h>

#define NG 32
#define NN 2048
#define NT 65536           // NG*NN
#define NE 1048576
#define NHEADS 8
#define F 12               // GAT_OUT
#define FH 96              // NHEADS*F
#define OUTC 9

// ---------------- scratch (static device memory only) ----------------
// per (n,h) 32B record: { asrc f32 | 12 x f16 channels | pad }
__device__ __align__(16) uint4 g_rec[NT * NHEADS * 2];
__device__ float g_adst[NT * NHEADS];
__device__ int   g_deg[NT];            // zero-initialized (BSS); re-zeroed by k_scan3 each run
__device__ int   g_off[NT + 1];
__device__ int   g_cur[NT];
__device__ int   g_bsum[64];
__device__ int   g_csr[NE];            // src ids grouped by dst
__device__ __align__(16) float g_post[F * NT];       // post log_softmax, channel-major [t][gn]
__device__ __align__(16) float g_wT1[NN * 128];      // w_ih1^T  [n][j]
__device__ __align__(16) float g_xp1[F * NG * 128];  // LSTM1 input projection
__device__ __align__(16) float g_hs2[F * NG * 128];

__device__ __forceinline__ float lrelu(float v) { return v > 0.f ? v : 0.2f * v; }
__device__ __forceinline__ float sigf(float v) { return 1.0f / (1.0f + __expf(-v)); }

// ---- prep: transpose w_ih1, xp = x@W + logits, pack records, AND edge histogram ----
__global__ void k_prep(const float* __restrict__ x, const float* __restrict__ W,
                       const float* __restrict__ av_s, const float* __restrict__ av_d,
                       const float* __restrict__ w1, const int* __restrict__ ei) {
    __shared__ float Ws[F * FH];
    __shared__ float as_s[FH], ad_s[FH];
    for (int i = threadIdx.x; i < F * FH; i += blockDim.x) Ws[i] = W[i];
    for (int i = threadIdx.x; i < FH; i += blockDim.x) { as_s[i] = av_s[i]; ad_s[i] = av_d[i]; }
    __syncthreads();

    int gid = blockIdx.x * blockDim.x + threadIdx.x;   // 0 .. 524287 = n*8+h
    if (gid < NN * 128) { int n = gid >> 7, j = gid & 127; g_wT1[gid] = w1[j * NN + n]; }

    // histogram: 2 edges per thread (g_deg starts at zero each run)
    atomicAdd(&g_deg[ei[NE + gid]], 1);
    atomicAdd(&g_deg[ei[NE + gid + NT * NHEADS]], 1);

    int n = gid >> 3, h = gid & 7;
    const float4* xv = reinterpret_cast<const float4*>(x + n * F);
    float4 v0 = xv[0], v1 = xv[1], v2 = xv[2];
    float xr[F] = {v0.x, v0.y, v0.z, v0.w, v1.x, v1.y, v1.z, v1.w, v2.x, v2.y, v2.z, v2.w};

    float o[F];
    float sa = 0.f, sd = 0.f;
#pragma unroll
    for (int c = 0; c < F; c++) {
        float s = 0.f;
#pragma unroll
        for (int k = 0; k < F; k++) s += xr[k] * Ws[k * FH + h * F + c];
        o[c] = s;
        sa += s * as_s[h * F + c];
        sd += s * ad_s[h * F + c];
    }
    uint4 r0, r1;
    r0.x = __float_as_uint(sa);
    __half2 p;
    p = __floats2half2_rn(o[0], o[1]);   r0.y = *reinterpret_cast<unsigned*>(&p);
    p = __floats2half2_rn(o[2], o[3]);   r0.z = *reinterpret_cast<unsigned*>(&p);
    p = __floats2half2_rn(o[4], o[5]);   r0.w = *reinterpret_cast<unsigned*>(&p);
    p = __floats2half2_rn(o[6], o[7]);   r1.x = *reinterpret_cast<unsigned*>(&p);
    p = __floats2half2_rn(o[8], o[9]);   r1.y = *reinterpret_cast<unsigned*>(&p);
    p = __floats2half2_rn(o[10], o[11]); r1.z = *reinterpret_cast<unsigned*>(&p);
    r1.w = 0u;
    g_rec[gid * 2]     = r0;
    g_rec[gid * 2 + 1] = r1;
    g_adst[gid] = sd;
}

__global__ void k_scan1() {
    int tid = threadIdx.x;
    int g = blockIdx.x * 1024 + tid;
    int lane = tid & 31, wid = tid >> 5;
    int v = g_deg[g];
    int incl = v;
#pragma unroll
    for (int off = 1; off < 32; off <<= 1) {
        int t = __shfl_up_sync(0xffffffffu, incl, off);
        if (lane >= off) incl += t;
    }
    __shared__ int wsum[32];
    if (lane == 31) wsum[wid] = incl;
    __syncthreads();
    if (wid == 0) {
        int s = wsum[lane];
        int si = s;
#pragma unroll
        for (int off = 1; off < 32; off <<= 1) {
            int t = __shfl_up_sync(0xffffffffu, si, off);
            if (lane >= off) si += t;
        }
        wsum[lane] = si - s;
    }
    __syncthreads();
    incl += wsum[wid];
    g_off[g] = incl - v;
    if (tid == 1023) g_bsum[blockIdx.x] = incl;
}

// applies block prefixes; also re-zeroes g_deg for the next graph replay
__global__ void k_scan3() {
    __shared__ int tmp[64];
    __shared__ int pre;
    int tid = threadIdx.x;
    if (tid < 64) tmp[tid] = g_bsum[tid];
    __syncthreads();
    if (tid == 0) {
        int s = 0;
        int nb = blockIdx.x;
        for (int i = 0; i < nb; i++) s += tmp[i];
        pre = s;
    }
    __syncthreads();
    int g = blockIdx.x * 1024 + tid;
    int o = g_off[g] + pre;
    g_off[g] = o;
    g_cur[g] = o;
    g_deg[g] = 0;
    if (g == 0) g_off[NT] = NE;
}

__global__ void k_scatter(const int* __restrict__ ei) {
    int e = blockIdx.x * blockDim.x + threadIdx.x;
    if (e < NE) {
        int d = ei[NE + e];
        int s = ei[e];
        int pos = atomicAdd(&g_cur[d], 1);
        g_csr[pos] = s;
    }
}

// ---- GAT aggregation: 4-edge software pipeline (MLP~8) + head-mean + BN + log_softmax ----
__global__ void __launch_bounds__(256) k_gat(
        const float* __restrict__ bias, const float* __restrict__ gamma,
        const float* __restrict__ beta, const float* __restrict__ mean,
        const float* __restrict__ var) {
    __shared__ float sb[F], sg[F], sbe[F], smn[F], svr[F];
    if (threadIdx.x < F) {
        sb[threadIdx.x]  = bias[threadIdx.x];
        sg[threadIdx.x]  = gamma[threadIdx.x];
        sbe[threadIdx.x] = beta[threadIdx.x];
        smn[threadIdx.x] = mean[threadIdx.x];
        svr[threadIdx.x] = var[threadIdx.x];
    }
    __syncthreads();

    int gid = blockIdx.x * blockDim.x + threadIdx.x;   // n*8 + h
    int n = gid >> 3, h = gid & 7;
    float adn = g_adst[gid];
    int st = g_off[n], en = g_off[n + 1];

    float denom = 0.f;
    float acc[F];
#pragma unroll
    for (int c = 0; c < F; c++) acc[c] = 0.f;

#define ACC2(r0, r1)                                                           \
    {                                                                          \
        float w = __expf(lrelu(__uint_as_float(r0.x) + adn));                  \
        denom += w;                                                            \
        __half2 hp; float2 f2;                                                 \
        hp = *reinterpret_cast<__half2*>(&r0.y); f2 = __half22float2(hp);      \
        acc[0] += w * f2.x; acc[1] += w * f2.y;                                \
        hp = *reinterpret_cast<__half2*>(&r0.z); f2 = __half22float2(hp);      \
        acc[2] += w * f2.x; acc[3] += w * f2.y;                                \
        hp = *reinterpret_cast<__half2*>(&r0.w); f2 = __half22float2(hp);      \
        acc[4] += w * f2.x; acc[5] += w * f2.y;                                \
        hp = *reinterpret_cast<__half2*>(&r1.x); f2 = __half22float2(hp);      \
        acc[6] += w * f2.x; acc[7] += w * f2.y;                                \
        hp = *reinterpret_cast<__half2*>(&r1.y); f2 = __half22float2(hp);      \
        acc[8] += w * f2.x; acc[9] += w * f2.y;                                \
        hp = *reinterpret_cast<__half2*>(&r1.z); f2 = __half22float2(hp);      \
        acc[10] += w * f2.x; acc[11] += w * f2.y;                              \
    }

    // self loop
    {
        uint4 a0 = g_rec[(unsigned)gid * 2u], a1 = g_rec[(unsigned)gid * 2u + 1u];
        ACC2(a0, a1);
    }
    int i = st;
    for (; i + 4 <= en; i += 4) {
        int s0 = g_csr[i], s1 = g_csr[i + 1], s2 = g_csr[i + 2], s3 = g_csr[i + 3];
        const uint4* p0 = &g_rec[(unsigned)(s0 * NHEADS + h) * 2u];
        const uint4* p1 = &g_rec[(unsigned)(s1 * NHEADS + h) * 2u];
        const uint4* p2 = &g_rec[(unsigned)(s2 * NHEADS + h) * 2u];
        const uint4* p3 = &g_rec[(unsigned)(s3 * NHEADS + h) * 2u];
        uint4 a0 = p0[0], a1 = p0[1];
        uint4 b0 = p1[0], b1 = p1[1];
        uint4 c0 = p2[0], c1 = p2[1];
        uint4 d0 = p3[0], d1 = p3[1];
        ACC2(a0, a1); ACC2(b0, b1); ACC2(c0, c1); ACC2(d0, d1);
    }
    for (; i < en; i++) {
        int s = g_csr[i];
        const uint4* rp = &g_rec[(unsigned)(s * NHEADS + h) * 2u];
        uint4 a0 = rp[0], a1 = rp[1];
        ACC2(a0, a1);
    }
#undef ACC2

    float inv = 1.f / (denom + 1e-16f);
#pragma unroll
    for (int c = 0; c < F; c++) acc[c] *= inv;

#pragma unroll
    for (int s = 4; s > 0; s >>= 1)
#pragma unroll
        for (int c = 0; c < F; c++) acc[c] += __shfl_xor_sync(0xffffffffu, acc[c], s);

    if (h == 0) {
        float v[F];
#pragma unroll
        for (int c = 0; c < F; c++) {
            float t = acc[c] * 0.125f + sb[c];
            v[c] = (t - smn[c]) * rsqrtf(svr[c] + 1e-5f) * sg[c] + sbe[c];
        }
        float mx = v[0];
#pragma unroll
        for (int c = 1; c < F; c++) mx = fmaxf(mx, v[c]);
        float ssum = 0.f;
#pragma unroll
        for (int c = 0; c < F; c++) ssum += __expf(v[c] - mx);
        float lz = mx + __logf(ssum);
#pragma unroll
        for (int c = 0; c < F; c++) g_post[c * NT + n] = v[c] - lz;
    }
}

// ---------------- LSTM1 input projection (all 12 timesteps) ----------------
__global__ void k_xproj1(const float* __restrict__ bih1, const float* __restrict__ bhh1) {
    int t = blockIdx.x >> 3;
    int bs = (blockIdx.x & 7) * 4;
    __shared__ float sp[4][256];
    float acc[4] = {0.f, 0.f, 0.f, 0.f};
    for (int n0 = 0; n0 < NN; n0 += 256) {
        __syncthreads();
        for (int i = threadIdx.x; i < 4 * 256; i += 128) {
            int q = i >> 8, ii = i & 255;
            sp[q][ii] = g_post[t * NT + (bs + q) * NN + n0 + ii];
        }
        __syncthreads();
#pragma unroll 4
        for (int ii = 0; ii < 256; ii++) {
            float w = g_wT1[(n0 + ii) * 128 + threadIdx.x];
            acc[0] += sp[0][ii] * w;
            acc[1] += sp[1][ii] * w;
            acc[2] += sp[2][ii] * w;
            acc[3] += sp[3][ii] * w;
        }
    }
    float bia = bih1[threadIdx.x] + bhh1[threadIdx.x];
#pragma unroll
    for (int q = 0; q < 4; q++)
        g_xp1[t * (NG * 128) + (bs + q) * 128 + threadIdx.x] = acc[q] + bia;
}

// -------- fused LSTM1 recurrence + LSTM2 (clusters of 2, weights staged in smem) --------
#define LSTM2_SMEM (256 * 129 * 4)

__global__ void __cluster_dims__(2, 1, 1) __launch_bounds__(256, 1)
k_lstm12(const float* __restrict__ whh1, const float* __restrict__ whh2,
         const float* __restrict__ wih2, const float* __restrict__ bih2,
         const float* __restrict__ bhh2) {
    extern __shared__ float wsm[];                  // [256 rows][129] padded
    __shared__ __align__(16) float h2buf[2][128];
    __shared__ float gs[256];
    __shared__ __align__(16) float xs12[F * 32];    // LSTM1 outputs for this batch
    __shared__ __align__(16) float h1s[32];

    int tid = threadIdx.x;
    int b = blockIdx.x >> 1;
    unsigned r;
    asm("mov.u32 %0, %%cluster_ctarank;" : "=r"(r));

    int gt = tid >> 6, l = tid & 63;
    int jglob = gt * 128 + (int)r * 64 + l;

    // stage this block's 256 w_hh2 rows
    for (int idx = tid; idx < 256 * 128; idx += 256) {
        int jl = idx >> 7, k = idx & 127;
        int jg2 = (jl >> 6) * 128 + (int)r * 64 + (jl & 63);
        wsm[jl * 129 + k] = whh2[jg2 * 128 + k];
    }
    float wi[32];
    {
        const float4* wr = reinterpret_cast<const float4*>(wih2 + jglob * 32);
#pragma unroll
        for (int q = 0; q < 8; q++) {
            float4 v = wr[q];
            wi[4 * q] = v.x; wi[4 * q + 1] = v.y; wi[4 * q + 2] = v.z; wi[4 * q + 3] = v.w;
        }
    }
    float bb = bih2[jglob] + bhh2[jglob];
    float c2_reg = 0.f;
    if (tid < 128) h2buf[0][tid] = 0.f;
    if (tid < 32) h1s[tid] = 0.f;

    unsigned peer_h2, peer_xs;
    {
        unsigned a = (unsigned)__cvta_generic_to_shared(&h2buf[0][0]);
        asm("mapa.shared::cluster.u32 %0, %1, %2;" : "=r"(peer_h2) : "r"(a), "r"(r ^ 1u));
        unsigned ax = (unsigned)__cvta_generic_to_shared(&xs12[0]);
        asm("mapa.shared::cluster.u32 %0, %1, %2;" : "=r"(peer_xs) : "r"(ax), "r"(r ^ 1u));
    }

    // ---- LSTM1 recurrence on rank 0 only ----
    if (r == 0) {
        float w1reg[32];
        if (tid < 128) {
            const float4* wr = reinterpret_cast<const float4*>(whh1 + tid * 32);
#pragma unroll
            for (int q = 0; q < 8; q++) {
                float4 v = wr[q];
                w1reg[4 * q] = v.x; w1reg[4 * q + 1] = v.y;
                w1reg[4 * q + 2] = v.z; w1reg[4 * q + 3] = v.w;
            }
        }
        float c1_reg = 0.f;
        __syncthreads();
        for (int t = 0; t < F; t++) {
            if (tid < 128) {
                float v = g_xp1[t * 4096 + b * 128 + tid];
                const float4* hv = reinterpret_cast<const float4*>(h1s);
#pragma unroll
                for (int q = 0; q < 8; q++) {
                    float4 h4 = hv[q];
                    v += h4.x * w1reg[4 * q] + h4.y * w1reg[4 * q + 1]
                       + h4.z * w1reg[4 * q + 2] + h4.w * w1reg[4 * q + 3];
                }
                gs[tid] = v;
            }
            __syncthreads();
            if (tid < 32) {
                float ig = gs[tid], fg = gs[32 + tid], gg = gs[64 + tid], og = gs[96 + tid];
                float cc = sigf(fg) * c1_reg + sigf(ig) * tanhf(gg);
                c1_reg = cc;
                float hh = sigf(og) * tanhf(cc);
                h1s[tid] = hh;
                xs12[t * 32 + tid] = hh;
            }
            __syncthreads();
        }
        // push LSTM1 outputs to peer (rank 1)
        for (int idx = tid; idx < F * 32; idx += 256)
            asm volatile("st.shared::cluster.f32 [%0], %1;"
                         :: "r"(peer_xs + (unsigned)(idx * 4)), "f"(xs12[idx]) : "memory");
    } else {
        __syncthreads();
    }
    asm volatile("barrier.cluster.arrive.aligned;" ::: "memory");
    asm volatile("barrier.cluster.wait.aligned;" ::: "memory");

    // ---- LSTM2 recurrence ----
    const float* wrow = &wsm[tid * 129];
    for (int t = 0; t < F; t++) {
        int cur = t & 1, nxt = cur ^ 1;
        float v = bb;
        const float4* xv = reinterpret_cast<const float4*>(&xs12[t * 32]);
#pragma unroll
        for (int q = 0; q < 8; q++) {
            float4 x4 = xv[q];
            v += x4.x * wi[4 * q] + x4.y * wi[4 * q + 1] + x4.z * wi[4 * q + 2] + x4.w * wi[4 * q + 3];
        }
        const float4* hv = reinterpret_cast<const float4*>(h2buf[cur]);
#pragma unroll
        for (int kk = 0; kk < 32; kk++) {
            float4 h4 = hv[kk];
            v += h4.x * wrow[4 * kk] + h4.y * wrow[4 * kk + 1]
               + h4.z * wrow[4 * kk + 2] + h4.w * wrow[4 * kk + 3];
        }
        gs[tid] = v;
        __syncthreads();
        if (tid < 64) {
            float ig = gs[tid], fg = gs[64 + tid], gg = gs[128 + tid], og = gs[192 + tid];
            float cc = sigf(fg) * c2_reg + sigf(ig) * tanhf(gg);
            c2_reg = cc;
            float hh = sigf(og) * tanhf(cc);
            int jc = (int)r * 64 + tid;
            h2buf[nxt][jc] = hh;
            asm volatile("st.shared::cluster.f32 [%0], %1;"
                         :: "r"(peer_h2 + (unsigned)((nxt * 128 + jc) * 4)), "f"(hh) : "memory");
            if (t >= 3) g_hs2[t * (NG * 128) + b * 128 + jc] = hh;
        }
        asm volatile("barrier.cluster.arrive.aligned;" ::: "memory");
        asm volatile("barrier.cluster.wait.aligned;" ::: "memory");
    }
}

// ---------------- final linear for last 9 timesteps ----------------
__global__ void k_final(const float* __restrict__ linw, const float* __restrict__ linb,
                        float* __restrict__ out) {
    int b = blockIdx.x >> 4;
    int c0 = (blockIdx.x & 15) * 128;
    __shared__ __align__(16) float sh[OUTC * 128];
    for (int i = threadIdx.x; i < OUTC * 128; i += blockDim.x) {
        int k = i >> 7, j = i & 127;
        sh[i] = g_hs2[(3 + k) * (NG * 128) + b * 128 + j];
    }
    __syncthreads();
    int warp = threadIdx.x >> 5, lane = threadIdx.x & 31;
    for (int idx = 0; idx < 16; idx++) {
        int n = c0 + warp * 16 + idx;
        float4 w4 = reinterpret_cast<const float4*>(linw + n * 128)[lane];
        float acc[OUTC];
#pragma unroll
        for (int k = 0; k < OUTC; k++) {
            float4 h4 = *reinterpret_cast<float4*>(&sh[k * 128 + lane * 4]);
            acc[k] = w4.x * h4.x + w4.y * h4.y + w4.z * h4.z + w4.w * h4.w;
        }
#pragma unroll
        for (int s = 16; s > 0; s >>= 1)
#pragma unroll
            for (int k = 0; k < OUTC; k++) acc[k] += __shfl_xor_sync(0xffffffffu, acc[k], s);
        if (lane == 0) {
            float lb = linb[n];
            float* o = out + (size_t)(b * NN + n) * OUTC;
#pragma unroll
            for (int k = 0; k < OUTC; k++) o[k] = acc[k] + lb;
        }
    }
}

// ---------------- launch ----------------
extern "C" void kernel_launch(void* const* d_in, const int* in_sizes, int n_in,
                              void* d_out, int out_size) {
    const float* x     = (const float*)d_in[0];
    const int*   ei    = (const int*)d_in[1];     // int32: JAX x64 disabled
    const float* Wg    = (const float*)d_in[2];
    const float* a_src = (const float*)d_in[3];
    const float* a_dst = (const float*)d_in[4];
    const float* gbias = (const float*)d_in[5];
    const float* gamma = (const float*)d_in[6];
    const float* beta  = (const float*)d_in[7];
    const float* mean  = (const float*)d_in[8];
    const float* var   = (const float*)d_in[9];
    const float* wih1  = (const float*)d_in[10];
    const float* whh1  = (const float*)d_in[11];
    const float* bih1  = (const float*)d_in[12];
    const float* bhh1  = (const float*)d_in[13];
    const float* wih2  = (const float*)d_in[14];
    const float* whh2  = (const float*)d_in[15];
    const float* bih2  = (const float*)d_in[16];
    const float* bhh2  = (const float*)d_in[17];
    const float* linw  = (const float*)d_in[18];
    const float* linb  = (const float*)d_in[19];
    float* out = (float*)d_out;

    cudaFuncSetAttribute(k_lstm12, cudaFuncAttributeMaxDynamicSharedMemorySize, LSTM2_SMEM);

    k_prep<<<NT * NHEADS / 256, 256>>>(x, Wg, a_src, a_dst, wih1, ei);
    k_scan1<<<64, 1024>>>();
    k_scan3<<<64, 1024>>>();
    k_scatter<<<NE / 256, 256>>>(ei);
    k_gat<<<NT * NHEADS / 256, 256>>>(gbias, gamma, beta, mean, var);
    k_xproj1<<<96, 128>>>(bih1, bhh1);
    k_lstm12<<<NG * 2, 256, LSTM2_SMEM>>>(whh1, whh2, wih2, bih2, bhh2);
    k_final<<<NG * 16, 256>>>(linw, linb, out);
}